// round 1
// baseline (speedup 1.0000x reference)
#include <cuda_runtime.h>
#include <math.h>

#define BATCH 2
#define SEQ   2048
#define DIM   4096
#define KV_DIM 1024
#define NHQ   32
#define NHK   8
#define HD    128
#define MROWS (BATCH*SEQ)

// -------- scratch (no allocations allowed) --------
__device__ float g_q[MROWS*DIM];
__device__ float g_k[MROWS*KV_DIM];
__device__ float g_v[MROWS*KV_DIM];
__device__ float g_attn[MROWS*DIM];

// ==================================================================
// GEMM (NT):  C[M,N] = A[M,K] * B[N,K]^T     (both row-major, K contig)
// BM=BN=128, BK=16, 256 threads, 8x8 micro-tile per thread.
// ==================================================================
#define BM 128
#define BN 128
#define BK 16

__global__ __launch_bounds__(256)
void gemm_nt(const float* __restrict__ A, const float* __restrict__ B,
             float* __restrict__ C, int M, int N, int K)
{
    __shared__ float As[BK][132];   // transposed tile, padded (132) for banks
    __shared__ float Bs[BK][132];

    const int tid = threadIdx.x;
    const int tx = tid & 15;        // 0..15 -> N micro
    const int ty = tid >> 4;        // 0..15 -> M micro
    const int m0 = blockIdx.y * BM;
    const int n0 = blockIdx.x * BN;

    float acc[8][8];
#pragma unroll
    for (int i = 0; i < 8; i++)
#pragma unroll
        for (int j = 0; j < 8; j++) acc[i][j] = 0.f;

    const int arow = tid >> 2;        // 0..63
    const int ak4  = (tid & 3) * 4;   // 0,4,8,12
    const float* Ab = A + (long)m0 * K;
    const float* Bb = B + (long)n0 * K;

    for (int k0 = 0; k0 < K; k0 += BK) {
#pragma unroll
        for (int h = 0; h < 2; h++) {
            int r = arow + h * 64;
            float4 va = *(const float4*)(Ab + (long)r * K + k0 + ak4);
            As[ak4+0][r] = va.x; As[ak4+1][r] = va.y;
            As[ak4+2][r] = va.z; As[ak4+3][r] = va.w;
            float4 vb = *(const float4*)(Bb + (long)r * K + k0 + ak4);
            Bs[ak4+0][r] = vb.x; Bs[ak4+1][r] = vb.y;
            Bs[ak4+2][r] = vb.z; Bs[ak4+3][r] = vb.w;
        }
        __syncthreads();

#pragma unroll
        for (int k = 0; k < BK; k++) {
            float4 a0 = *(const float4*)&As[k][ty * 4];
            float4 a1 = *(const float4*)&As[k][64 + ty * 4];
            float4 b0 = *(const float4*)&Bs[k][tx * 4];
            float4 b1 = *(const float4*)&Bs[k][64 + tx * 4];
            float a[8] = {a0.x,a0.y,a0.z,a0.w,a1.x,a1.y,a1.z,a1.w};
            float b[8] = {b0.x,b0.y,b0.z,b0.w,b1.x,b1.y,b1.z,b1.w};
#pragma unroll
            for (int i = 0; i < 8; i++)
#pragma unroll
                for (int j = 0; j < 8; j++)
                    acc[i][j] += a[i] * b[j];
        }
        __syncthreads();
    }

#pragma unroll
    for (int i = 0; i < 8; i++) {
        int r = m0 + ((i < 4) ? (ty * 4 + i) : (64 + ty * 4 + (i - 4)));
        float4 c0 = make_float4(acc[i][0], acc[i][1], acc[i][2], acc[i][3]);
        float4 c1 = make_float4(acc[i][4], acc[i][5], acc[i][6], acc[i][7]);
        *(float4*)(C + (long)r * N + n0 + tx * 4)      = c0;
        *(float4*)(C + (long)r * N + n0 + 64 + tx * 4) = c1;
    }
}

// ==================================================================
// RoPE (interleaved pairs, matches reference fp32 rounding)
// ==================================================================
__global__ void rope_kernel(float* __restrict__ x, const int* __restrict__ sp,
                            int nh, int stride)
{
    int idx = blockIdx.x * blockDim.x + threadIdx.x;   // over rows*nh*64
    int i   = idx & 63;
    int h   = (idx >> 6) % nh;
    int row = idx / (64 * nh);
    int pos = (row % SEQ) + sp[0];

    float invf = (float)pow(10000.0, -(double)i / 64.0);
    float ang  = __fmul_rn((float)pos, invf);
    float sn, cs;
    sincosf(ang, &sn, &cs);

    float2* p = (float2*)(x + (long)row * stride + h * HD);
    float2 v = p[i];
    float o0 = v.x * cs - v.y * sn;
    float o1 = v.x * sn + v.y * cs;
    p[i] = make_float2(o0, o1);
}

// ==================================================================
// Flash attention (fp32), GQA 32Q/8KV heads, hd=128, full (no mask)
// BQ=64, BKT=64, 256 threads. tx=tid&15 (dims/k-cols), ty=tid>>4 (q-rows)
// Thread owns q rows {ty+16i}, score cols {tx+16j}, out dims
// {4tx..4tx+3, 64+4tx..64+4tx+3}.
// ==================================================================
#define QROW_STRIDE 132
#define P_STRIDE    68
#define ATTN_SMEM ((2*64*QROW_STRIDE + 64*P_STRIDE) * 4)

__global__ __launch_bounds__(256)
void attn_kernel(const float* __restrict__ Q, const float* __restrict__ Kg,
                 const float* __restrict__ Vg, float* __restrict__ O)
{
    extern __shared__ float sm[];
    float* Qs = sm;                        // [64][132]
    float* Ks = sm + 64 * QROW_STRIDE;     // [64][132]  (K, then reused for V)
    float* Ps = sm + 2 * 64 * QROW_STRIDE; // [64][68]

    const int tid = threadIdx.x;
    const int tx = tid & 15;
    const int ty = tid >> 4;
    const int qt = blockIdx.x;
    const int h  = blockIdx.y;
    const int b  = blockIdx.z;
    const int hk = h >> 2;
    const int q0 = qt * 64;
    const float scale = 0.08838834764831845f;   // 1/sqrt(128)

    // load Q tile
    {
        int c4 = tid & 31;
        int r0 = tid >> 5;
        for (int rr = r0; rr < 64; rr += 8) {
            float4 v = *(const float4*)(Q + (long)(b * SEQ + q0 + rr) * DIM + h * HD + c4 * 4);
            *(float4*)(Qs + rr * QROW_STRIDE + c4 * 4) = v;
        }
    }

    float acc[4][8];
#pragma unroll
    for (int i = 0; i < 4; i++)
#pragma unroll
        for (int j = 0; j < 8; j++) acc[i][j] = 0.f;
    float mrow[4], lrow[4];
#pragma unroll
    for (int i = 0; i < 4; i++) { mrow[i] = -1e30f; lrow[i] = 0.f; }

    for (int kt = 0; kt < SEQ / 64; kt++) {
        int k0 = kt * 64;
        // load K tile
        {
            int c4 = tid & 31;
            int r0 = tid >> 5;
            for (int rr = r0; rr < 64; rr += 8) {
                float4 v = *(const float4*)(Kg + (long)(b * SEQ + k0 + rr) * KV_DIM + hk * HD + c4 * 4);
                *(float4*)(Ks + rr * QROW_STRIDE + c4 * 4) = v;
            }
        }
        __syncthreads();

        // scores s[i][j]: q = ty+16i, k = tx+16j
        float s[4][4];
#pragma unroll
        for (int i = 0; i < 4; i++)
#pragma unroll
            for (int j = 0; j < 4; j++) s[i][j] = 0.f;

#pragma unroll 4
        for (int d4 = 0; d4 < 32; d4++) {
            float4 qv[4], kv[4];
#pragma unroll
            for (int i = 0; i < 4; i++)
                qv[i] = *(const float4*)(Qs + (ty + 16 * i) * QROW_STRIDE + d4 * 4);
#pragma unroll
            for (int j = 0; j < 4; j++)
                kv[j] = *(const float4*)(Ks + (tx + 16 * j) * QROW_STRIDE + d4 * 4);
#pragma unroll
            for (int i = 0; i < 4; i++)
#pragma unroll
                for (int j = 0; j < 4; j++)
                    s[i][j] += qv[i].x * kv[j].x + qv[i].y * kv[j].y +
                               qv[i].z * kv[j].z + qv[i].w * kv[j].w;
        }

        // online softmax per q row (half-warp reductions; lanes 0-15/16-31 groups)
#pragma unroll
        for (int i = 0; i < 4; i++) {
#pragma unroll
            for (int j = 0; j < 4; j++) s[i][j] *= scale;
            float mx = fmaxf(fmaxf(s[i][0], s[i][1]), fmaxf(s[i][2], s[i][3]));
#pragma unroll
            for (int o = 1; o < 16; o <<= 1)
                mx = fmaxf(mx, __shfl_xor_sync(0xffffffffu, mx, o));
            float mnew = fmaxf(mrow[i], mx);
            float cf = __expf(mrow[i] - mnew);
            float p[4], psum = 0.f;
#pragma unroll
            for (int j = 0; j < 4; j++) { p[j] = __expf(s[i][j] - mnew); psum += p[j]; }
#pragma unroll
            for (int o = 1; o < 16; o <<= 1)
                psum += __shfl_xor_sync(0xffffffffu, psum, o);
            lrow[i] = lrow[i] * cf + psum;
            mrow[i] = mnew;
#pragma unroll
            for (int j = 0; j < 8; j++) acc[i][j] *= cf;
#pragma unroll
            for (int j = 0; j < 4; j++)
                Ps[(ty + 16 * i) * P_STRIDE + tx + 16 * j] = p[j];
        }
        __syncthreads();   // Ps written; K reads done

        // load V tile into Ks buffer
        {
            int c4 = tid & 31;
            int r0 = tid >> 5;
            for (int rr = r0; rr < 64; rr += 8) {
                float4 v = *(const float4*)(Vg + (long)(b * SEQ + k0 + rr) * KV_DIM + hk * HD + c4 * 4);
                *(float4*)(Ks + rr * QROW_STRIDE + c4 * 4) = v;
            }
        }
        __syncthreads();

        // O += P * V
#pragma unroll 2
        for (int k = 0; k < 64; k++) {
            float pk[4];
#pragma unroll
            for (int i = 0; i < 4; i++) pk[i] = Ps[(ty + 16 * i) * P_STRIDE + k];
            float4 v0 = *(const float4*)(Ks + k * QROW_STRIDE + tx * 4);
            float4 v1 = *(const float4*)(Ks + k * QROW_STRIDE + 64 + tx * 4);
#pragma unroll
            for (int i = 0; i < 4; i++) {
                acc[i][0] += pk[i] * v0.x; acc[i][1] += pk[i] * v0.y;
                acc[i][2] += pk[i] * v0.z; acc[i][3] += pk[i] * v0.w;
                acc[i][4] += pk[i] * v1.x; acc[i][5] += pk[i] * v1.y;
                acc[i][6] += pk[i] * v1.z; acc[i][7] += pk[i] * v1.w;
            }
        }
        __syncthreads();   // done with Ks/Ps before next tile
    }

    // epilogue
#pragma unroll
    for (int i = 0; i < 4; i++) {
        float rinv = 1.f / lrow[i];
        int q = q0 + ty + 16 * i;
        float* op = O + (long)(b * SEQ + q) * DIM + h * HD;
        float4 o0 = make_float4(acc[i][0] * rinv, acc[i][1] * rinv,
                                acc[i][2] * rinv, acc[i][3] * rinv);
        float4 o1 = make_float4(acc[i][4] * rinv, acc[i][5] * rinv,
                                acc[i][6] * rinv, acc[i][7] * rinv);
        *(float4*)(op + tx * 4)      = o0;
        *(float4*)(op + 64 + tx * 4) = o1;
    }
}

// ==================================================================
// Launch
// ==================================================================
extern "C" void kernel_launch(void* const* d_in, const int* in_sizes, int n_in,
                              void* d_out, int out_size)
{
    (void)in_sizes; (void)n_in; (void)out_size;
    const float* x  = (const float*)d_in[0];
    const float* wq = (const float*)d_in[1];
    const float* wk = (const float*)d_in[2];
    const float* wv = (const float*)d_in[3];
    const float* wo = (const float*)d_in[4];
    const int*   sp = (const int*)d_in[5];
    float* out = (float*)d_out;

    float *q, *k, *v, *attn;
    cudaGetSymbolAddress((void**)&q,    g_q);
    cudaGetSymbolAddress((void**)&k,    g_k);
    cudaGetSymbolAddress((void**)&v,    g_v);
    cudaGetSymbolAddress((void**)&attn, g_attn);

    cudaFuncSetAttribute(attn_kernel,
                         cudaFuncAttributeMaxDynamicSharedMemorySize, ATTN_SMEM);

    dim3 gq(DIM / BN,    MROWS / BM);
    dim3 gkv(KV_DIM / BN, MROWS / BM);
    gemm_nt<<<gq, 256>>>(x, wq, q, MROWS, DIM,    DIM);
    gemm_nt<<<gkv, 256>>>(x, wk, k, MROWS, KV_DIM, DIM);
    gemm_nt<<<gkv, 256>>>(x, wv, v, MROWS, KV_DIM, DIM);

    rope_kernel<<<(MROWS * NHQ * 64) / 256, 256>>>(q, sp, NHQ, DIM);
    rope_kernel<<<(MROWS * NHK * 64) / 256, 256>>>(k, sp, NHK, KV_DIM);

    dim3 ga(SEQ / 64, NHQ, BATCH);
    attn_kernel<<<ga, 256, ATTN_SMEM>>>(q, k, v, attn);

    gemm_nt<<<gq, 256>>>(attn, wo, out, MROWS, DIM, DIM);
}

// round 4
// speedup vs baseline: 1.0603x; 1.0603x over previous
#include <cuda_runtime.h>
#include <cstdint>
#include <math.h>

#define BATCH 2
#define SEQ   2048
#define DIM   4096
#define KV_DIM 1024
#define NHQ   32
#define NHK   8
#define HD    128
#define MROWS (BATCH*SEQ)

// scratch (no allocations allowed)
__device__ float g_q[MROWS*DIM];
__device__ float g_k[MROWS*KV_DIM];
__device__ float g_v[MROWS*KV_DIM];
__device__ float g_attn[MROWS*DIM];

// ==================================================================
// helpers
// ==================================================================
__device__ __forceinline__ uint32_t f2tf32(float x)
{
    uint32_t u;
    asm("cvt.rna.tf32.f32 %0, %1;" : "=r"(u) : "f"(x));
    return u;
}

__device__ __forceinline__ void ldsm4(uint32_t& r0, uint32_t& r1,
                                      uint32_t& r2, uint32_t& r3, uint32_t addr)
{
    asm volatile("ldmatrix.sync.aligned.m8n8.x4.shared.b16 {%0,%1,%2,%3}, [%4];"
                 : "=r"(r0), "=r"(r1), "=r"(r2), "=r"(r3) : "r"(addr));
}

__device__ __forceinline__ void mma_tf32(float* d, const uint32_t* a,
                                         uint32_t b0, uint32_t b1)
{
    asm volatile("mma.sync.aligned.m16n8k8.row.col.f32.tf32.tf32.f32 "
                 "{%0,%1,%2,%3},{%4,%5,%6,%7},{%8,%9},{%0,%1,%2,%3};"
                 : "+f"(d[0]), "+f"(d[1]), "+f"(d[2]), "+f"(d[3])
                 : "r"(a[0]), "r"(a[1]), "r"(a[2]), "r"(a[3]),
                   "r"(b0), "r"(b1));
}

// ==================================================================
// TF32 GEMM (NT): C[M,N] = A[M,K] * B[N,K]^T
// 128x128x32 tile, 256 threads = 8 warps (4 along M x 2 along N),
// each warp 32x64. Double-buffered swizzled smem + ldmatrix.
// ==================================================================
#define GBM 128
#define GBN 128
#define GBK 32
#define GEMM_SMEM 65536

__global__ __launch_bounds__(256)
void gemm_tf32(const float* __restrict__ A, const float* __restrict__ B,
               float* __restrict__ C, int M, int N, int K)
{
    extern __shared__ uint4 gsm[];   // [A0 1024 | B0 1024 | A1 1024 | B1 1024]
    const uint32_t su = (uint32_t)__cvta_generic_to_shared(gsm);

    const int tid  = threadIdx.x;
    const int lane = tid & 31;
    const int warp = tid >> 5;
    const int wm   = warp & 3;
    const int wn   = warp >> 2;
    const int bm   = blockIdx.y;
    const int bn   = blockIdx.x;

    const int lrow  = tid >> 3;
    const int lcol4 = tid & 7;
    const int lswz  = lcol4 ^ (lrow & 7);
    const float* Ap = A + (long)(bm * GBM + lrow) * K + lcol4 * 4;
    const float* Bp = B + (long)(bn * GBN + lrow) * K + lcol4 * 4;

    const int grp = lane >> 3;
    const int lr  = lane & 7;
    const int rowA = wm * 32 + lr + 8 * (grp & 1);
    const int gA   = grp >> 1;
    const int swzA = rowA & 7;
    const int rowB = wn * 64 + lr + 8 * (grp >> 1);
    const int gB   = grp & 1;
    const int swzB = rowB & 7;
    const uint32_t aRowOff = (uint32_t)rowA * 128u;
    const uint32_t bRowOff = (uint32_t)rowB * 128u;

    float c[2][8][4];
    for (int mt = 0; mt < 2; mt++) {
        for (int nt = 0; nt < 8; nt++) {
            for (int r = 0; r < 4; r++) {
                c[mt][nt][r] = 0.f;
            }
        }
    }

    float4 av[4];
    float4 bv[4];

    // prologue: load k-slab 0 and stage into buffer 0
    for (int p = 0; p < 4; p++) {
        av[p] = *(const float4*)(Ap + (long)(p * 32) * K);
        bv[p] = *(const float4*)(Bp + (long)(p * 32) * K);
    }
    for (int p = 0; p < 4; p++) {
        uint4 ua = make_uint4(f2tf32(av[p].x), f2tf32(av[p].y),
                              f2tf32(av[p].z), f2tf32(av[p].w));
        uint4 ub = make_uint4(f2tf32(bv[p].x), f2tf32(bv[p].y),
                              f2tf32(bv[p].z), f2tf32(bv[p].w));
        gsm[(lrow + 32 * p) * 8 + lswz]        = ua;
        gsm[1024 + (lrow + 32 * p) * 8 + lswz] = ub;
    }
    __syncthreads();

    int buf = 0;
    for (int k0 = 0; k0 < K; k0 += GBK) {
        const bool last = (k0 + GBK >= K);
        if (!last) {
            for (int p = 0; p < 4; p++) {
                av[p] = *(const float4*)(Ap + (long)(p * 32) * K + k0 + GBK);
                bv[p] = *(const float4*)(Bp + (long)(p * 32) * K + k0 + GBK);
            }
        }

        const uint32_t Abase = su + (uint32_t)buf * 32768u;
        const uint32_t Bbase = su + 16384u + (uint32_t)buf * 32768u;

#pragma unroll
        for (int kk = 0; kk < 4; kk++) {
            uint32_t af0[4];
            uint32_t af1[4];
            uint32_t aAddr = Abase + aRowOff + (uint32_t)(((2 * kk + gA) ^ swzA) << 4);
            ldsm4(af0[0], af0[1], af0[2], af0[3], aAddr);
            ldsm4(af1[0], af1[1], af1[2], af1[3], aAddr + 2048u);

            uint32_t bf[4][4];
#pragma unroll
            for (int jp = 0; jp < 4; jp++) {
                uint32_t bAddr = Bbase + bRowOff + (uint32_t)(jp * 2048) +
                                 (uint32_t)(((2 * kk + gB) ^ swzB) << 4);
                ldsm4(bf[jp][0], bf[jp][1], bf[jp][2], bf[jp][3], bAddr);
            }

#pragma unroll
            for (int nt = 0; nt < 8; nt++) {
                uint32_t b0 = bf[nt >> 1][(nt & 1) * 2];
                uint32_t b1 = bf[nt >> 1][(nt & 1) * 2 + 1];
                mma_tf32(c[0][nt], af0, b0, b1);
                mma_tf32(c[1][nt], af1, b0, b1);
            }
        }

        if (!last) {
            int nb = buf ^ 1;
            for (int p = 0; p < 4; p++) {
                uint4 ua = make_uint4(f2tf32(av[p].x), f2tf32(av[p].y),
                                      f2tf32(av[p].z), f2tf32(av[p].w));
                uint4 ub = make_uint4(f2tf32(bv[p].x), f2tf32(bv[p].y),
                                      f2tf32(bv[p].z), f2tf32(bv[p].w));
                gsm[nb * 2048 + (lrow + 32 * p) * 8 + lswz]        = ua;
                gsm[nb * 2048 + 1024 + (lrow + 32 * p) * 8 + lswz] = ub;
            }
        }
        __syncthreads();
        buf ^= 1;
    }

    const int g  = lane >> 2;
    const int t2 = (lane & 3) * 2;
    for (int mt = 0; mt < 2; mt++) {
        int row0 = bm * GBM + wm * 32 + mt * 16 + g;
        for (int nt = 0; nt < 8; nt++) {
            int col = bn * GBN + wn * 64 + nt * 8 + t2;
            *(float2*)(C + (long)row0 * N + col)       = make_float2(c[mt][nt][0], c[mt][nt][1]);
            *(float2*)(C + (long)(row0 + 8) * N + col) = make_float2(c[mt][nt][2], c[mt][nt][3]);
        }
    }
}

// ==================================================================
// RoPE
// ==================================================================
__global__ void rope_kernel(float* __restrict__ x, const int* __restrict__ sp,
                            int nh, int stride)
{
    int idx = blockIdx.x * blockDim.x + threadIdx.x;
    int i   = idx & 63;
    int h   = (idx >> 6) % nh;
    int row = idx / (64 * nh);
    int pos = (row % SEQ) + sp[0];

    float invf = (float)pow(10000.0, -(double)i / 64.0);
    float ang  = __fmul_rn((float)pos, invf);
    float sn;
    float cs;
    sincosf(ang, &sn, &cs);

    float2* p = (float2*)(x + (long)row * stride + h * HD);
    float2 v = p[i];
    p[i] = make_float2(v.x * cs - v.y * sn, v.x * sn + v.y * cs);
}

// ==================================================================
// Flash attention (fp32) — proven in round 1
// ==================================================================
#define QROW_STRIDE 132
#define P_STRIDE    68
#define ATTN_SMEM ((2*64*QROW_STRIDE + 64*P_STRIDE) * 4)

__global__ __launch_bounds__(256)
void attn_kernel(const float* __restrict__ Q, const float* __restrict__ Kg,
                 const float* __restrict__ Vg, float* __restrict__ O)
{
    extern __shared__ float asm_[];
    float* Qs = asm_;
    float* Ks = asm_ + 64 * QROW_STRIDE;
    float* Ps = asm_ + 2 * 64 * QROW_STRIDE;

    const int tid = threadIdx.x;
    const int tx = tid & 15;
    const int ty = tid >> 4;
    const int qt = blockIdx.x;
    const int h  = blockIdx.y;
    const int b  = blockIdx.z;
    const int hk = h >> 2;
    const int q0 = qt * 64;
    const float scale = 0.08838834764831845f;

    {
        int c4 = tid & 31;
        int r0 = tid >> 5;
        for (int rr = r0; rr < 64; rr += 8) {
            float4 v = *(const float4*)(Q + (long)(b * SEQ + q0 + rr) * DIM + h * HD + c4 * 4);
            *(float4*)(Qs + rr * QROW_STRIDE + c4 * 4) = v;
        }
    }

    float acc[4][8];
    for (int i = 0; i < 4; i++) {
        for (int j = 0; j < 8; j++) {
            acc[i][j] = 0.f;
        }
    }
    float mrow[4];
    float lrow[4];
    for (int i = 0; i < 4; i++) {
        mrow[i] = -1e30f;
        lrow[i] = 0.f;
    }

    for (int kt = 0; kt < SEQ / 64; kt++) {
        int k0 = kt * 64;
        {
            int c4 = tid & 31;
            int r0 = tid >> 5;
            for (int rr = r0; rr < 64; rr += 8) {
                float4 v = *(const float4*)(Kg + (long)(b * SEQ + k0 + rr) * KV_DIM + hk * HD + c4 * 4);
                *(float4*)(Ks + rr * QROW_STRIDE + c4 * 4) = v;
            }
        }
        __syncthreads();

        float s[4][4];
        for (int i = 0; i < 4; i++) {
            for (int j = 0; j < 4; j++) {
                s[i][j] = 0.f;
            }
        }

#pragma unroll 4
        for (int d4 = 0; d4 < 32; d4++) {
            float4 qv[4];
            float4 kv[4];
#pragma unroll
            for (int i = 0; i < 4; i++) {
                qv[i] = *(const float4*)(Qs + (ty + 16 * i) * QROW_STRIDE + d4 * 4);
            }
#pragma unroll
            for (int j = 0; j < 4; j++) {
                kv[j] = *(const float4*)(Ks + (tx + 16 * j) * QROW_STRIDE + d4 * 4);
            }
#pragma unroll
            for (int i = 0; i < 4; i++) {
#pragma unroll
                for (int j = 0; j < 4; j++) {
                    s[i][j] += qv[i].x * kv[j].x + qv[i].y * kv[j].y +
                               qv[i].z * kv[j].z + qv[i].w * kv[j].w;
                }
            }
        }

#pragma unroll
        for (int i = 0; i < 4; i++) {
#pragma unroll
            for (int j = 0; j < 4; j++) {
                s[i][j] *= scale;
            }
            float mx = fmaxf(fmaxf(s[i][0], s[i][1]), fmaxf(s[i][2], s[i][3]));
#pragma unroll
            for (int o = 1; o < 16; o <<= 1) {
                mx = fmaxf(mx, __shfl_xor_sync(0xffffffffu, mx, o));
            }
            float mnew = fmaxf(mrow[i], mx);
            float cf = __expf(mrow[i] - mnew);
            float p[4];
            float psum = 0.f;
#pragma unroll
            for (int j = 0; j < 4; j++) {
                p[j] = __expf(s[i][j] - mnew);
                psum += p[j];
            }
#pragma unroll
            for (int o = 1; o < 16; o <<= 1) {
                psum += __shfl_xor_sync(0xffffffffu, psum, o);
            }
            lrow[i] = lrow[i] * cf + psum;
            mrow[i] = mnew;
#pragma unroll
            for (int j = 0; j < 8; j++) {
                acc[i][j] *= cf;
            }
#pragma unroll
            for (int j = 0; j < 4; j++) {
                Ps[(ty + 16 * i) * P_STRIDE + tx + 16 * j] = p[j];
            }
        }
        __syncthreads();

        {
            int c4 = tid & 31;
            int r0 = tid >> 5;
            for (int rr = r0; rr < 64; rr += 8) {
                float4 v = *(const float4*)(Vg + (long)(b * SEQ + k0 + rr) * KV_DIM + hk * HD + c4 * 4);
                *(float4*)(Ks + rr * QROW_STRIDE + c4 * 4) = v;
            }
        }
        __syncthreads();

#pragma unroll 2
        for (int k = 0; k < 64; k++) {
            float pk[4];
#pragma unroll
            for (int i = 0; i < 4; i++) {
                pk[i] = Ps[(ty + 16 * i) * P_STRIDE + k];
            }
            float4 v0 = *(const float4*)(Ks + k * QROW_STRIDE + tx * 4);
            float4 v1 = *(const float4*)(Ks + k * QROW_STRIDE + 64 + tx * 4);
#pragma unroll
            for (int i = 0; i < 4; i++) {
                acc[i][0] += pk[i] * v0.x;
                acc[i][1] += pk[i] * v0.y;
                acc[i][2] += pk[i] * v0.z;
                acc[i][3] += pk[i] * v0.w;
                acc[i][4] += pk[i] * v1.x;
                acc[i][5] += pk[i] * v1.y;
                acc[i][6] += pk[i] * v1.z;
                acc[i][7] += pk[i] * v1.w;
            }
        }
        __syncthreads();
    }

    for (int i = 0; i < 4; i++) {
        float rinv = 1.f / lrow[i];
        int q = q0 + ty + 16 * i;
        float* op = O + (long)(b * SEQ + q) * DIM + h * HD;
        *(float4*)(op + tx * 4) =
            make_float4(acc[i][0]*rinv, acc[i][1]*rinv, acc[i][2]*rinv, acc[i][3]*rinv);
        *(float4*)(op + 64 + tx * 4) =
            make_float4(acc[i][4]*rinv, acc[i][5]*rinv, acc[i][6]*rinv, acc[i][7]*rinv);
    }
}

// ==================================================================
// Launch
// ==================================================================
extern "C" void kernel_launch(void* const* d_in, const int* in_sizes, int n_in,
                              void* d_out, int out_size)
{
    (void)in_sizes;
    (void)n_in;
    (void)out_size;
    const float* x  = (const float*)d_in[0];
    const float* wq = (const float*)d_in[1];
    const float* wk = (const float*)d_in[2];
    const float* wv = (const float*)d_in[3];
    const float* wo = (const float*)d_in[4];
    const int*   sp = (const int*)d_in[5];
    float* out = (float*)d_out;

    float* q;
    float* k;
    float* v;
    float* attn;
    cudaGetSymbolAddress((void**)&q,    g_q);
    cudaGetSymbolAddress((void**)&k,    g_k);
    cudaGetSymbolAddress((void**)&v,    g_v);
    cudaGetSymbolAddress((void**)&attn, g_attn);

    cudaFuncSetAttribute(gemm_tf32,
                         cudaFuncAttributeMaxDynamicSharedMemorySize, GEMM_SMEM);
    cudaFuncSetAttribute(attn_kernel,
                         cudaFuncAttributeMaxDynamicSharedMemorySize, ATTN_SMEM);

    dim3 gq(DIM / GBN, MROWS / GBM);
    dim3 gkv(KV_DIM / GBN, MROWS / GBM);
    gemm_tf32<<<gq,  256, GEMM_SMEM>>>(x, wq, q, MROWS, DIM,    DIM);
    gemm_tf32<<<gkv, 256, GEMM_SMEM>>>(x, wk, k, MROWS, KV_DIM, DIM);
    gemm_tf32<<<gkv, 256, GEMM_SMEM>>>(x, wv, v, MROWS, KV_DIM, DIM);

    rope_kernel<<<(MROWS * NHQ * 64) / 256, 256>>>(q, sp, NHQ, DIM);
    rope_kernel<<<(MROWS * NHK * 64) / 256, 256>>>(k, sp, NHK, KV_DIM);

    dim3 ga(SEQ / 64, NHQ, BATCH);
    attn_kernel<<<ga, 256, ATTN_SMEM>>>(q, k, v, attn);

    gemm_tf32<<<gq, 256, GEMM_SMEM>>>(attn, wo, out, MROWS, DIM, DIM);
}

// round 5
// speedup vs baseline: 1.7995x; 1.6971x over previous
#include <cuda_runtime.h>
#include <cstdint>
#include <math.h>

#define BATCH 2
#define SEQ   2048
#define DIM   4096
#define KV_DIM 1024
#define NHQ   32
#define NHK   8
#define HD    128
#define MROWS (BATCH*SEQ)

// scratch (no allocations allowed)
__device__ float g_q[MROWS*DIM];
__device__ float g_k[MROWS*KV_DIM];
__device__ float g_v[MROWS*KV_DIM];
__device__ float g_attn[MROWS*DIM];
// tf32-pre-rounded operands
__device__ float g_rx[MROWS*DIM];
__device__ float g_rwq[DIM*DIM];
__device__ float g_rwk[KV_DIM*DIM];
__device__ float g_rwv[KV_DIM*DIM];
__device__ float g_rwo[DIM*DIM];

// ==================================================================
// helpers
// ==================================================================
__device__ __forceinline__ uint32_t f2tf32(float x)
{
    uint32_t u;
    asm("cvt.rna.tf32.f32 %0, %1;" : "=r"(u) : "f"(x));
    return u;
}

__device__ __forceinline__ void ldsm4(uint32_t& r0, uint32_t& r1,
                                      uint32_t& r2, uint32_t& r3, uint32_t addr)
{
    asm volatile("ldmatrix.sync.aligned.m8n8.x4.shared.b16 {%0,%1,%2,%3}, [%4];"
                 : "=r"(r0), "=r"(r1), "=r"(r2), "=r"(r3) : "r"(addr));
}

__device__ __forceinline__ void mma_tf32(float* d, const uint32_t* a,
                                         uint32_t b0, uint32_t b1)
{
    asm volatile("mma.sync.aligned.m16n8k8.row.col.f32.tf32.tf32.f32 "
                 "{%0,%1,%2,%3},{%4,%5,%6,%7},{%8,%9},{%0,%1,%2,%3};"
                 : "+f"(d[0]), "+f"(d[1]), "+f"(d[2]), "+f"(d[3])
                 : "r"(a[0]), "r"(a[1]), "r"(a[2]), "r"(a[3]),
                   "r"(b0), "r"(b1));
}

__device__ __forceinline__ void cp_async16(uint32_t dst, const void* src)
{
    asm volatile("cp.async.cg.shared.global [%0], [%1], 16;" :: "r"(dst), "l"(src));
}
__device__ __forceinline__ void cp_commit()
{
    asm volatile("cp.async.commit_group;");
}
template<int N> __device__ __forceinline__ void cp_wait()
{
    asm volatile("cp.async.wait_group %0;" :: "n"(N));
}

// ==================================================================
// pre-round to tf32 (rna) — bandwidth bound, ~80us total
// ==================================================================
__global__ void round_tf32_kernel(const float* __restrict__ in,
                                  float* __restrict__ out, int n4)
{
    int i = blockIdx.x * blockDim.x + threadIdx.x;
    if (i < n4) {
        float4 v = ((const float4*)in)[i];
        uint4 u = make_uint4(f2tf32(v.x), f2tf32(v.y), f2tf32(v.z), f2tf32(v.w));
        ((uint4*)out)[i] = u;
    }
}

// ==================================================================
// TF32 GEMM (NT), cp.async 3-stage pipeline.
// C[M,N] = A[M,K]*B[N,K]^T, A/B pre-rounded to tf32 bit patterns.
// 128x128x32 tile, 256 threads = 8 warps (4 M x 2 N), warp tile 32x64.
// ==================================================================
#define GBM 128
#define GBN 128
#define GBK 32
#define STAGES 3
#define STAGE_BYTES 32768
#define GEMM_SMEM (STAGES*STAGE_BYTES)   // 96KB

__global__ __launch_bounds__(256, 2)
void gemm_tf32(const float* __restrict__ A, const float* __restrict__ B,
               float* __restrict__ C, int M, int N, int K)
{
    extern __shared__ uint4 gsm[];
    const uint32_t su = (uint32_t)__cvta_generic_to_shared(gsm);

    const int tid  = threadIdx.x;
    const int lane = tid & 31;
    const int warp = tid >> 5;
    const int wm   = warp & 3;
    const int wn   = warp >> 2;
    const int bm   = blockIdx.y;
    const int bn   = blockIdx.x;

    // loader mapping: 16B per thread, 4 rows each of A and B per stage
    const int lrow  = tid >> 3;          // 0..31
    const int lcol4 = tid & 7;           // 0..7
    const int lswz  = lcol4 ^ (lrow & 7);
    const float* Ap = A + (long)(bm * GBM + lrow) * K + lcol4 * 4;
    const float* Bp = B + (long)(bn * GBN + lrow) * K + lcol4 * 4;
    const uint32_t aDst = su + (uint32_t)((lrow * 8 + lswz) * 16);
    const uint32_t bDst = aDst + 16384u;

    // ldmatrix lane constants
    const int grp = lane >> 3;
    const int lr  = lane & 7;
    const int rowA = wm * 32 + lr + 8 * (grp & 1);
    const int gA   = grp >> 1;
    const int swzA = rowA & 7;
    const int rowB = wn * 64 + lr + 8 * (grp >> 1);
    const int gB   = grp & 1;
    const int swzB = rowB & 7;
    const uint32_t aRowOff = (uint32_t)rowA * 128u;
    const uint32_t bRowOff = (uint32_t)rowB * 128u;

    float c[2][8][4];
    for (int mt = 0; mt < 2; mt++) {
        for (int nt = 0; nt < 8; nt++) {
            for (int r = 0; r < 4; r++) {
                c[mt][nt][r] = 0.f;
            }
        }
    }

    const int T = K / GBK;

    // prologue: stages 0..STAGES-2
    for (int s = 0; s < STAGES - 1; s++) {
        uint32_t ad = aDst + (uint32_t)s * STAGE_BYTES;
        uint32_t bd = bDst + (uint32_t)s * STAGE_BYTES;
        int kof = s * GBK;
#pragma unroll
        for (int p = 0; p < 4; p++) {
            cp_async16(ad + (uint32_t)(p * 32 * 128), Ap + (long)(p * 32) * K + kof);
            cp_async16(bd + (uint32_t)(p * 32 * 128), Bp + (long)(p * 32) * K + kof);
        }
        cp_commit();
    }

    for (int ks = 0; ks < T; ks++) {
        cp_wait<STAGES - 2>();
        __syncthreads();

        // issue stage ks+STAGES-1
        int nk = ks + STAGES - 1;
        if (nk < T) {
            int slot = nk % STAGES;
            uint32_t ad = aDst + (uint32_t)slot * STAGE_BYTES;
            uint32_t bd = bDst + (uint32_t)slot * STAGE_BYTES;
            int kof = nk * GBK;
#pragma unroll
            for (int p = 0; p < 4; p++) {
                cp_async16(ad + (uint32_t)(p * 32 * 128), Ap + (long)(p * 32) * K + kof);
                cp_async16(bd + (uint32_t)(p * 32 * 128), Bp + (long)(p * 32) * K + kof);
            }
            cp_commit();
        }

        // compute stage ks%STAGES
        const uint32_t Abase = su + (uint32_t)((ks % STAGES) * STAGE_BYTES);
        const uint32_t Bbase = Abase + 16384u;

#pragma unroll
        for (int kk = 0; kk < 4; kk++) {
            uint32_t af0[4];
            uint32_t af1[4];
            uint32_t aAddr = Abase + aRowOff + (uint32_t)(((2 * kk + gA) ^ swzA) << 4);
            ldsm4(af0[0], af0[1], af0[2], af0[3], aAddr);
            ldsm4(af1[0], af1[1], af1[2], af1[3], aAddr + 2048u);

            uint32_t bf[4][4];
#pragma unroll
            for (int jp = 0; jp < 4; jp++) {
                uint32_t bAddr = Bbase + bRowOff + (uint32_t)(jp * 2048) +
                                 (uint32_t)(((2 * kk + gB) ^ swzB) << 4);
                ldsm4(bf[jp][0], bf[jp][1], bf[jp][2], bf[jp][3], bAddr);
            }

#pragma unroll
            for (int nt = 0; nt < 8; nt++) {
                uint32_t b0 = bf[nt >> 1][(nt & 1) * 2];
                uint32_t b1 = bf[nt >> 1][(nt & 1) * 2 + 1];
                mma_tf32(c[0][nt], af0, b0, b1);
                mma_tf32(c[1][nt], af1, b0, b1);
            }
        }
    }

    const int g  = lane >> 2;
    const int t2 = (lane & 3) * 2;
    for (int mt = 0; mt < 2; mt++) {
        int row0 = bm * GBM + wm * 32 + mt * 16 + g;
        for (int nt = 0; nt < 8; nt++) {
            int col = bn * GBN + wn * 64 + nt * 8 + t2;
            *(float2*)(C + (long)row0 * N + col)       = make_float2(c[mt][nt][0], c[mt][nt][1]);
            *(float2*)(C + (long)(row0 + 8) * N + col) = make_float2(c[mt][nt][2], c[mt][nt][3]);
        }
    }
}

// ==================================================================
// RoPE
// ==================================================================
__global__ void rope_kernel(float* __restrict__ x, const int* __restrict__ sp,
                            int nh, int stride)
{
    int idx = blockIdx.x * blockDim.x + threadIdx.x;
    int i   = idx & 63;
    int h   = (idx >> 6) % nh;
    int row = idx / (64 * nh);
    int pos = (row % SEQ) + sp[0];

    float invf = (float)pow(10000.0, -(double)i / 64.0);
    float ang  = __fmul_rn((float)pos, invf);
    float sn;
    float cs;
    sincosf(ang, &sn, &cs);

    float2* p = (float2*)(x + (long)row * stride + h * HD);
    float2 v = p[i];
    p[i] = make_float2(v.x * cs - v.y * sn, v.x * sn + v.y * cs);
}

// ==================================================================
// Flash attention (fp32) — unchanged (proven)
// ==================================================================
#define QROW_STRIDE 132
#define P_STRIDE    68
#define ATTN_SMEM ((2*64*QROW_STRIDE + 64*P_STRIDE) * 4)

__global__ __launch_bounds__(256)
void attn_kernel(const float* __restrict__ Q, const float* __restrict__ Kg,
                 const float* __restrict__ Vg, float* __restrict__ O)
{
    extern __shared__ float asm_[];
    float* Qs = asm_;
    float* Ks = asm_ + 64 * QROW_STRIDE;
    float* Ps = asm_ + 2 * 64 * QROW_STRIDE;

    const int tid = threadIdx.x;
    const int tx = tid & 15;
    const int ty = tid >> 4;
    const int qt = blockIdx.x;
    const int h  = blockIdx.y;
    const int b  = blockIdx.z;
    const int hk = h >> 2;
    const int q0 = qt * 64;
    const float scale = 0.08838834764831845f;

    {
        int c4 = tid & 31;
        int r0 = tid >> 5;
        for (int rr = r0; rr < 64; rr += 8) {
            float4 v = *(const float4*)(Q + (long)(b * SEQ + q0 + rr) * DIM + h * HD + c4 * 4);
            *(float4*)(Qs + rr * QROW_STRIDE + c4 * 4) = v;
        }
    }

    float acc[4][8];
    for (int i = 0; i < 4; i++) {
        for (int j = 0; j < 8; j++) {
            acc[i][j] = 0.f;
        }
    }
    float mrow[4];
    float lrow[4];
    for (int i = 0; i < 4; i++) {
        mrow[i] = -1e30f;
        lrow[i] = 0.f;
    }

    for (int kt = 0; kt < SEQ / 64; kt++) {
        int k0 = kt * 64;
        {
            int c4 = tid & 31;
            int r0 = tid >> 5;
            for (int rr = r0; rr < 64; rr += 8) {
                float4 v = *(const float4*)(Kg + (long)(b * SEQ + k0 + rr) * KV_DIM + hk * HD + c4 * 4);
                *(float4*)(Ks + rr * QROW_STRIDE + c4 * 4) = v;
            }
        }
        __syncthreads();

        float s[4][4];
        for (int i = 0; i < 4; i++) {
            for (int j = 0; j < 4; j++) {
                s[i][j] = 0.f;
            }
        }

#pragma unroll 4
        for (int d4 = 0; d4 < 32; d4++) {
            float4 qv[4];
            float4 kv[4];
#pragma unroll
            for (int i = 0; i < 4; i++) {
                qv[i] = *(const float4*)(Qs + (ty + 16 * i) * QROW_STRIDE + d4 * 4);
            }
#pragma unroll
            for (int j = 0; j < 4; j++) {
                kv[j] = *(const float4*)(Ks + (tx + 16 * j) * QROW_STRIDE + d4 * 4);
            }
#pragma unroll
            for (int i = 0; i < 4; i++) {
#pragma unroll
                for (int j = 0; j < 4; j++) {
                    s[i][j] += qv[i].x * kv[j].x + qv[i].y * kv[j].y +
                               qv[i].z * kv[j].z + qv[i].w * kv[j].w;
                }
            }
        }

#pragma unroll
        for (int i = 0; i < 4; i++) {
#pragma unroll
            for (int j = 0; j < 4; j++) {
                s[i][j] *= scale;
            }
            float mx = fmaxf(fmaxf(s[i][0], s[i][1]), fmaxf(s[i][2], s[i][3]));
#pragma unroll
            for (int o = 1; o < 16; o <<= 1) {
                mx = fmaxf(mx, __shfl_xor_sync(0xffffffffu, mx, o));
            }
            float mnew = fmaxf(mrow[i], mx);
            float cf = __expf(mrow[i] - mnew);
            float p[4];
            float psum = 0.f;
#pragma unroll
            for (int j = 0; j < 4; j++) {
                p[j] = __expf(s[i][j] - mnew);
                psum += p[j];
            }
#pragma unroll
            for (int o = 1; o < 16; o <<= 1) {
                psum += __shfl_xor_sync(0xffffffffu, psum, o);
            }
            lrow[i] = lrow[i] * cf + psum;
            mrow[i] = mnew;
#pragma unroll
            for (int j = 0; j < 8; j++) {
                acc[i][j] *= cf;
            }
#pragma unroll
            for (int j = 0; j < 4; j++) {
                Ps[(ty + 16 * i) * P_STRIDE + tx + 16 * j] = p[j];
            }
        }
        __syncthreads();

        {
            int c4 = tid & 31;
            int r0 = tid >> 5;
            for (int rr = r0; rr < 64; rr += 8) {
                float4 v = *(const float4*)(Vg + (long)(b * SEQ + k0 + rr) * KV_DIM + hk * HD + c4 * 4);
                *(float4*)(Ks + rr * QROW_STRIDE + c4 * 4) = v;
            }
        }
        __syncthreads();

#pragma unroll 2
        for (int k = 0; k < 64; k++) {
            float pk[4];
#pragma unroll
            for (int i = 0; i < 4; i++) {
                pk[i] = Ps[(ty + 16 * i) * P_STRIDE + k];
            }
            float4 v0 = *(const float4*)(Ks + k * QROW_STRIDE + tx * 4);
            float4 v1 = *(const float4*)(Ks + k * QROW_STRIDE + 64 + tx * 4);
#pragma unroll
            for (int i = 0; i < 4; i++) {
                acc[i][0] += pk[i] * v0.x;
                acc[i][1] += pk[i] * v0.y;
                acc[i][2] += pk[i] * v0.z;
                acc[i][3] += pk[i] * v0.w;
                acc[i][4] += pk[i] * v1.x;
                acc[i][5] += pk[i] * v1.y;
                acc[i][6] += pk[i] * v1.z;
                acc[i][7] += pk[i] * v1.w;
            }
        }
        __syncthreads();
    }

    for (int i = 0; i < 4; i++) {
        float rinv = 1.f / lrow[i];
        int q = q0 + ty + 16 * i;
        float* op = O + (long)(b * SEQ + q) * DIM + h * HD;
        *(float4*)(op + tx * 4) =
            make_float4(acc[i][0]*rinv, acc[i][1]*rinv, acc[i][2]*rinv, acc[i][3]*rinv);
        *(float4*)(op + 64 + tx * 4) =
            make_float4(acc[i][4]*rinv, acc[i][5]*rinv, acc[i][6]*rinv, acc[i][7]*rinv);
    }
}

// ==================================================================
// Launch
// ==================================================================
extern "C" void kernel_launch(void* const* d_in, const int* in_sizes, int n_in,
                              void* d_out, int out_size)
{
    (void)in_sizes;
    (void)n_in;
    (void)out_size;
    const float* x  = (const float*)d_in[0];
    const float* wq = (const float*)d_in[1];
    const float* wk = (const float*)d_in[2];
    const float* wv = (const float*)d_in[3];
    const float* wo = (const float*)d_in[4];
    const int*   sp = (const int*)d_in[5];
    float* out = (float*)d_out;

    float* q;
    float* k;
    float* v;
    float* attn;
    float* rx;
    float* rwq;
    float* rwk;
    float* rwv;
    float* rwo;
    cudaGetSymbolAddress((void**)&q,    g_q);
    cudaGetSymbolAddress((void**)&k,    g_k);
    cudaGetSymbolAddress((void**)&v,    g_v);
    cudaGetSymbolAddress((void**)&attn, g_attn);
    cudaGetSymbolAddress((void**)&rx,   g_rx);
    cudaGetSymbolAddress((void**)&rwq,  g_rwq);
    cudaGetSymbolAddress((void**)&rwk,  g_rwk);
    cudaGetSymbolAddress((void**)&rwv,  g_rwv);
    cudaGetSymbolAddress((void**)&rwo,  g_rwo);

    cudaFuncSetAttribute(gemm_tf32,
                         cudaFuncAttributeMaxDynamicSharedMemorySize, GEMM_SMEM);
    cudaFuncSetAttribute(attn_kernel,
                         cudaFuncAttributeMaxDynamicSharedMemorySize, ATTN_SMEM);

    // pre-round operands to tf32 (rna)
    {
        int n4x  = MROWS * DIM / 4;
        int n4q  = DIM * DIM / 4;
        int n4kv = KV_DIM * DIM / 4;
        round_tf32_kernel<<<(n4x  + 255) / 256, 256>>>(x,  rx,  n4x);
        round_tf32_kernel<<<(n4q  + 255) / 256, 256>>>(wq, rwq, n4q);
        round_tf32_kernel<<<(n4kv + 255) / 256, 256>>>(wk, rwk, n4kv);
        round_tf32_kernel<<<(n4kv + 255) / 256, 256>>>(wv, rwv, n4kv);
        round_tf32_kernel<<<(n4q  + 255) / 256, 256>>>(wo, rwo, n4q);
    }

    dim3 gq(DIM / GBN, MROWS / GBM);
    dim3 gkv(KV_DIM / GBN, MROWS / GBM);
    gemm_tf32<<<gq,  256, GEMM_SMEM>>>(rx, rwq, q, MROWS, DIM,    DIM);
    gemm_tf32<<<gkv, 256, GEMM_SMEM>>>(rx, rwk, k, MROWS, KV_DIM, DIM);
    gemm_tf32<<<gkv, 256, GEMM_SMEM>>>(rx, rwv, v, MROWS, KV_DIM, DIM);

    rope_kernel<<<(MROWS * NHQ * 64) / 256, 256>>>(q, sp, NHQ, DIM);
    rope_kernel<<<(MROWS * NHK * 64) / 256, 256>>>(k, sp, NHK, KV_DIM);

    dim3 ga(SEQ / 64, NHQ, BATCH);
    attn_kernel<<<ga, 256, ATTN_SMEM>>>(q, k, v, attn);

    // round attention output, then final projection
    {
        int n4x = MROWS * DIM / 4;
        round_tf32_kernel<<<(n4x + 255) / 256, 256>>>(attn, rx, n4x);
    }
    gemm_tf32<<<gq, 256, GEMM_SMEM>>>(rx, rwo, out, MROWS, DIM, DIM);
}

// round 6
// speedup vs baseline: 2.6246x; 1.4585x over previous
#include <cuda_runtime.h>
#include <cstdint>
#include <math.h>

#define BATCH 2
#define SEQ   2048
#define DIM   4096
#define KV_DIM 1024
#define NHQ   32
#define NHK   8
#define HD    128
#define MROWS (BATCH*SEQ)

// scratch (no allocations allowed)
__device__ float g_q[MROWS*DIM];
__device__ float g_k[MROWS*KV_DIM];
__device__ float g_v[MROWS*KV_DIM];
__device__ float g_attn[MROWS*DIM];
__device__ float g_rx[MROWS*DIM];
__device__ float g_rwq[DIM*DIM];
__device__ float g_rwk[KV_DIM*DIM];
__device__ float g_rwv[KV_DIM*DIM];
__device__ float g_rwo[DIM*DIM];

// ==================================================================
// helpers
// ==================================================================
__device__ __forceinline__ uint32_t f2tf32(float x)
{
    uint32_t u;
    asm("cvt.rna.tf32.f32 %0, %1;" : "=r"(u) : "f"(x));
    return u;
}

__device__ __forceinline__ void ldsm4(uint32_t& r0, uint32_t& r1,
                                      uint32_t& r2, uint32_t& r3, uint32_t addr)
{
    asm volatile("ldmatrix.sync.aligned.m8n8.x4.shared.b16 {%0,%1,%2,%3}, [%4];"
                 : "=r"(r0), "=r"(r1), "=r"(r2), "=r"(r3) : "r"(addr));
}

__device__ __forceinline__ void mma_tf32(float* d, const uint32_t* a,
                                         uint32_t b0, uint32_t b1)
{
    asm volatile("mma.sync.aligned.m16n8k8.row.col.f32.tf32.tf32.f32 "
                 "{%0,%1,%2,%3},{%4,%5,%6,%7},{%8,%9},{%0,%1,%2,%3};"
                 : "+f"(d[0]), "+f"(d[1]), "+f"(d[2]), "+f"(d[3])
                 : "r"(a[0]), "r"(a[1]), "r"(a[2]), "r"(a[3]),
                   "r"(b0), "r"(b1));
}

__device__ __forceinline__ void cp_async16(uint32_t dst, const void* src)
{
    asm volatile("cp.async.cg.shared.global [%0], [%1], 16;" :: "r"(dst), "l"(src));
}
__device__ __forceinline__ void cp_commit()
{
    asm volatile("cp.async.commit_group;");
}
template<int N> __device__ __forceinline__ void cp_wait()
{
    asm volatile("cp.async.wait_group %0;" :: "n"(N));
}

// ==================================================================
// pre-round to tf32 (rna)
// ==================================================================
__global__ void round_tf32_kernel(const float* __restrict__ in,
                                  float* __restrict__ out, int n4)
{
    int i = blockIdx.x * blockDim.x + threadIdx.x;
    if (i < n4) {
        float4 v = ((const float4*)in)[i];
        uint4 u = make_uint4(f2tf32(v.x), f2tf32(v.y), f2tf32(v.z), f2tf32(v.w));
        ((uint4*)out)[i] = u;
    }
}

// ==================================================================
// TF32 GEMM (NT), cp.async 3-stage pipeline.  (unchanged from R5)
// ==================================================================
#define GBM 128
#define GBN 128
#define GBK 32
#define STAGES 3
#define STAGE_BYTES 32768
#define GEMM_SMEM (STAGES*STAGE_BYTES)

__global__ __launch_bounds__(256, 2)
void gemm_tf32(const float* __restrict__ A, const float* __restrict__ B,
               float* __restrict__ C, int M, int N, int K)
{
    extern __shared__ uint4 gsm[];
    const uint32_t su = (uint32_t)__cvta_generic_to_shared(gsm);

    const int tid  = threadIdx.x;
    const int lane = tid & 31;
    const int warp = tid >> 5;
    const int wm   = warp & 3;
    const int wn   = warp >> 2;
    const int bm   = blockIdx.y;
    const int bn   = blockIdx.x;

    const int lrow  = tid >> 3;
    const int lcol4 = tid & 7;
    const int lswz  = lcol4 ^ (lrow & 7);
    const float* Ap = A + (long)(bm * GBM + lrow) * K + lcol4 * 4;
    const float* Bp = B + (long)(bn * GBN + lrow) * K + lcol4 * 4;
    const uint32_t aDst = su + (uint32_t)((lrow * 8 + lswz) * 16);
    const uint32_t bDst = aDst + 16384u;

    const int grp = lane >> 3;
    const int lr  = lane & 7;
    const int rowA = wm * 32 + lr + 8 * (grp & 1);
    const int gA   = grp >> 1;
    const int swzA = rowA & 7;
    const int rowB = wn * 64 + lr + 8 * (grp >> 1);
    const int gB   = grp & 1;
    const int swzB = rowB & 7;
    const uint32_t aRowOff = (uint32_t)rowA * 128u;
    const uint32_t bRowOff = (uint32_t)rowB * 128u;

    float c[2][8][4];
    for (int mt = 0; mt < 2; mt++) {
        for (int nt = 0; nt < 8; nt++) {
            for (int r = 0; r < 4; r++) {
                c[mt][nt][r] = 0.f;
            }
        }
    }

    const int T = K / GBK;

    for (int s = 0; s < STAGES - 1; s++) {
        uint32_t ad = aDst + (uint32_t)s * STAGE_BYTES;
        uint32_t bd = bDst + (uint32_t)s * STAGE_BYTES;
        int kof = s * GBK;
#pragma unroll
        for (int p = 0; p < 4; p++) {
            cp_async16(ad + (uint32_t)(p * 32 * 128), Ap + (long)(p * 32) * K + kof);
            cp_async16(bd + (uint32_t)(p * 32 * 128), Bp + (long)(p * 32) * K + kof);
        }
        cp_commit();
    }

    for (int ks = 0; ks < T; ks++) {
        cp_wait<STAGES - 2>();
        __syncthreads();

        int nk = ks + STAGES - 1;
        if (nk < T) {
            int slot = nk % STAGES;
            uint32_t ad = aDst + (uint32_t)slot * STAGE_BYTES;
            uint32_t bd = bDst + (uint32_t)slot * STAGE_BYTES;
            int kof = nk * GBK;
#pragma unroll
            for (int p = 0; p < 4; p++) {
                cp_async16(ad + (uint32_t)(p * 32 * 128), Ap + (long)(p * 32) * K + kof);
                cp_async16(bd + (uint32_t)(p * 32 * 128), Bp + (long)(p * 32) * K + kof);
            }
            cp_commit();
        }

        const uint32_t Abase = su + (uint32_t)((ks % STAGES) * STAGE_BYTES);
        const uint32_t Bbase = Abase + 16384u;

#pragma unroll
        for (int kk = 0; kk < 4; kk++) {
            uint32_t af0[4];
            uint32_t af1[4];
            uint32_t aAddr = Abase + aRowOff + (uint32_t)(((2 * kk + gA) ^ swzA) << 4);
            ldsm4(af0[0], af0[1], af0[2], af0[3], aAddr);
            ldsm4(af1[0], af1[1], af1[2], af1[3], aAddr + 2048u);

            uint32_t bf[4][4];
#pragma unroll
            for (int jp = 0; jp < 4; jp++) {
                uint32_t bAddr = Bbase + bRowOff + (uint32_t)(jp * 2048) +
                                 (uint32_t)(((2 * kk + gB) ^ swzB) << 4);
                ldsm4(bf[jp][0], bf[jp][1], bf[jp][2], bf[jp][3], bAddr);
            }

#pragma unroll
            for (int nt = 0; nt < 8; nt++) {
                uint32_t b0 = bf[nt >> 1][(nt & 1) * 2];
                uint32_t b1 = bf[nt >> 1][(nt & 1) * 2 + 1];
                mma_tf32(c[0][nt], af0, b0, b1);
                mma_tf32(c[1][nt], af1, b0, b1);
            }
        }
    }

    const int g  = lane >> 2;
    const int t2 = (lane & 3) * 2;
    for (int mt = 0; mt < 2; mt++) {
        int row0 = bm * GBM + wm * 32 + mt * 16 + g;
        for (int nt = 0; nt < 8; nt++) {
            int col = bn * GBN + wn * 64 + nt * 8 + t2;
            *(float2*)(C + (long)row0 * N + col)       = make_float2(c[mt][nt][0], c[mt][nt][1]);
            *(float2*)(C + (long)(row0 + 8) * N + col) = make_float2(c[mt][nt][2], c[mt][nt][3]);
        }
    }
}

// ==================================================================
// RoPE: now also pre-scales (q) and rounds output to tf32
// ==================================================================
__global__ void rope_kernel(float* __restrict__ x, const int* __restrict__ sp,
                            int nh, int stride, float scale)
{
    int idx = blockIdx.x * blockDim.x + threadIdx.x;
    int i   = idx & 63;
    int h   = (idx >> 6) % nh;
    int row = idx / (64 * nh);
    int pos = (row % SEQ) + sp[0];

    float invf = (float)pow(10000.0, -(double)i / 64.0);
    float ang  = __fmul_rn((float)pos, invf);
    float sn;
    float cs;
    sincosf(ang, &sn, &cs);

    float2* p = (float2*)(x + (long)row * stride + h * HD);
    float2 v = p[i];
    float o0 = (v.x * cs - v.y * sn) * scale;
    float o1 = (v.x * sn + v.y * cs) * scale;
    p[i] = make_float2(__uint_as_float(f2tf32(o0)), __uint_as_float(f2tf32(o1)));
}

// ==================================================================
// Tensor-core flash attention (tf32 MMA, fp32 softmax)
// BQ=128 (8 warps x m16), KT=64, HD=128.
// Q/K/V already tf32-rounded; Q pre-scaled by 1/sqrt(HD).
// SMEM: K[2]:64KB | Vraw[2]:64KB | VT:36KB | Ps:36KB  (200KB)
// ==================================================================
#define AT_VRAW  65536
#define AT_VT    131072
#define AT_PS    168832         // 131072 + 128*288 (rounded to 16B: 36864 -> 168, use 131072+36864=167936)
#undef  AT_PS
#define AT_PS    167936
#define VT_STRIDE 288
#define ATTN_SMEM (167936 + 128*288)   // 204800

__global__ __launch_bounds__(256, 1)
void attn_tc_kernel(const float* __restrict__ Q, const float* __restrict__ Kg,
                    const float* __restrict__ Vg, float* __restrict__ O)
{
    extern __shared__ char smc[];
    const uint32_t su = (uint32_t)__cvta_generic_to_shared(smc);
    const int tid  = threadIdx.x;
    const int lane = tid & 31;
    const int warp = tid >> 5;
    const int qt = blockIdx.x;
    const int h  = blockIdx.y;
    const int b  = blockIdx.z;
    const int hk = h >> 2;
    const int q0 = qt * 128;

    const int grp = lane >> 3;
    const int lr  = lane & 7;
    const int arow = warp * 16 + lr + 8 * (grp & 1);  // A-side row (Q / P)
    const int gA   = grp >> 1;
    const int brow = lr + 8 * (grp >> 1);             // B-side row base (K / VT)
    const int gB   = grp & 1;

    // ---- stage Q (128x512B) into [0,64KB), ldmatrix to regs ----
    {
        int row = tid >> 1;
        int ub  = (tid & 1) * 16;
        const float* src = Q + (long)(b * SEQ + q0 + row) * DIM + h * HD;
#pragma unroll
        for (int p = 0; p < 16; p++) {
            int u  = ub + p;
            int uu = (u & 24) | ((u & 7) ^ (row & 7));
            cp_async16(su + (uint32_t)(row * 512 + uu * 16), src + u * 4);
        }
        cp_commit();
        cp_wait<0>();
        __syncthreads();
    }
    uint32_t qf[16][4];
    {
        uint32_t base = su + (uint32_t)(arow * 512);
#pragma unroll
        for (int kk = 0; kk < 16; kk++) {
            int u  = 2 * kk + gA;
            int uu = (u & 24) | ((u & 7) ^ (arow & 7));
            ldsm4(qf[kk][0], qf[kk][1], qf[kk][2], qf[kk][3], base + (uint32_t)(uu * 16));
        }
    }
    __syncthreads();   // Q consumed; K buffers free

    float oacc[16][4];
    for (int nt = 0; nt < 16; nt++) {
        for (int r = 0; r < 4; r++) {
            oacc[nt][r] = 0.f;
        }
    }
    float m0 = -1e30f, m1 = -1e30f, l0 = 0.f, l1 = 0.f;

    const int lkrow = tid >> 2;
    const int lku   = tid & 3;

    // K/V tile loader
    auto load_kv = [&](int kt2, int bb2) {
        long roff = (long)(b * SEQ + kt2 * 64 + lkrow);
        const float* ks = Kg + roff * KV_DIM + hk * HD;
        const float* vs = Vg + roff * KV_DIM + hk * HD;
        uint32_t kd = su + (uint32_t)(bb2 * 32768 + lkrow * 512);
        uint32_t vd = su + (uint32_t)(AT_VRAW + bb2 * 32768 + lkrow * 512);
#pragma unroll
        for (int p = 0; p < 8; p++) {
            int u  = lku + p * 4;
            int uu = (u & 24) | ((u & 7) ^ (lkrow & 7));
            cp_async16(kd + (uint32_t)(uu * 16), ks + u * 4);
            cp_async16(vd + (uint32_t)(uu * 16), vs + u * 4);
        }
    };

    load_kv(0, 0);
    cp_commit();
    load_kv(1, 1);
    cp_commit();

    for (int kt = 0; kt < 32; kt++) {
        cp_wait<1>();
        __syncthreads();    // tile kt ready; prev iter's PV reads of VT/Ps done

        int bb = kt & 1;
        const uint32_t Kbase = su + (uint32_t)(bb * 32768);
        const int vrawOff = AT_VRAW + bb * 32768;

        // (a) transpose V tile -> VT  (128 d-rows x 64 keys, stride 288B)
#pragma unroll
        for (int i = 0; i < 8; i++) {
            int idx = tid + i * 256;
            int r = idx >> 5;
            int u = idx & 31;
            int uu = (u & 24) | ((u & 7) ^ (r & 7));
            float4 v = *(const float4*)(smc + vrawOff + r * 512 + uu * 16);
            int d0  = u * 4;
            int vu  = r >> 2;
            int sub = r & 3;
            float vv4[4] = {v.x, v.y, v.z, v.w};
#pragma unroll
            for (int j = 0; j < 4; j++) {
                int d  = d0 + j;
                int vv = (vu & 8) | ((vu & 7) ^ (d & 7));
                *(float*)(smc + AT_VT + d * VT_STRIDE + vv * 16 + sub * 4) = vv4[j];
            }
        }

        // (b) S = Q * K^T   (16 q rows x 64 keys per warp)
        float sc[8][4];
        for (int nt = 0; nt < 8; nt++) {
            for (int r = 0; r < 4; r++) {
                sc[nt][r] = 0.f;
            }
        }
#pragma unroll
        for (int kk = 0; kk < 16; kk++) {
            uint32_t bf[4][4];
#pragma unroll
            for (int jp = 0; jp < 4; jp++) {
                int r  = jp * 16 + brow;
                int u  = 2 * kk + gB;
                int uu = (u & 24) | ((u & 7) ^ (r & 7));
                ldsm4(bf[jp][0], bf[jp][1], bf[jp][2], bf[jp][3],
                      Kbase + (uint32_t)(r * 512 + uu * 16));
            }
#pragma unroll
            for (int nt = 0; nt < 8; nt++) {
                mma_tf32(sc[nt], qf[kk],
                         bf[nt >> 1][(nt & 1) * 2], bf[nt >> 1][(nt & 1) * 2 + 1]);
            }
        }

        // (c) online softmax (rows: warp*16+g and +8), write P -> Ps
        {
            float mx0 = -1e30f, mx1 = -1e30f;
#pragma unroll
            for (int nt = 0; nt < 8; nt++) {
                mx0 = fmaxf(mx0, fmaxf(sc[nt][0], sc[nt][1]));
                mx1 = fmaxf(mx1, fmaxf(sc[nt][2], sc[nt][3]));
            }
            mx0 = fmaxf(mx0, __shfl_xor_sync(0xffffffffu, mx0, 1));
            mx0 = fmaxf(mx0, __shfl_xor_sync(0xffffffffu, mx0, 2));
            mx1 = fmaxf(mx1, __shfl_xor_sync(0xffffffffu, mx1, 1));
            mx1 = fmaxf(mx1, __shfl_xor_sync(0xffffffffu, mx1, 2));
            float nm0 = fmaxf(m0, mx0);
            float nm1 = fmaxf(m1, mx1);
            float cf0 = __expf(m0 - nm0);
            float cf1 = __expf(m1 - nm1);
            m0 = nm0;
            m1 = nm1;

            const int g  = lane >> 2;
            const int t2 = (lane & 3) * 2;
            const int prow0 = warp * 16 + g;
            const int prow1 = prow0 + 8;
            float ps0 = 0.f, ps1 = 0.f;
#pragma unroll
            for (int nt = 0; nt < 8; nt++) {
                float p0 = __expf(sc[nt][0] - nm0);
                float p1 = __expf(sc[nt][1] - nm0);
                float p2 = __expf(sc[nt][2] - nm1);
                float p3 = __expf(sc[nt][3] - nm1);
                ps0 += p0 + p1;
                ps1 += p2 + p3;
                int pu  = nt * 2 + (t2 >> 2);
                int pu0 = (pu & 8) | ((pu & 7) ^ (prow0 & 7));
                int pu1 = (pu & 8) | ((pu & 7) ^ (prow1 & 7));
                *(uint2*)(smc + AT_PS + prow0 * VT_STRIDE + pu0 * 16 + (t2 & 3) * 4) =
                    make_uint2(f2tf32(p0), f2tf32(p1));
                *(uint2*)(smc + AT_PS + prow1 * VT_STRIDE + pu1 * 16 + (t2 & 3) * 4) =
                    make_uint2(f2tf32(p2), f2tf32(p3));
            }
            ps0 += __shfl_xor_sync(0xffffffffu, ps0, 1);
            ps0 += __shfl_xor_sync(0xffffffffu, ps0, 2);
            ps1 += __shfl_xor_sync(0xffffffffu, ps1, 1);
            ps1 += __shfl_xor_sync(0xffffffffu, ps1, 2);
            l0 = l0 * cf0 + ps0;
            l1 = l1 * cf1 + ps1;
#pragma unroll
            for (int nt = 0; nt < 16; nt++) {
                oacc[nt][0] *= cf0;
                oacc[nt][1] *= cf0;
                oacc[nt][2] *= cf1;
                oacc[nt][3] *= cf1;
            }
        }
        __syncthreads();   // (d) VT+P written; all K-tile reads complete

        // (e) prefetch tile kt+2 into buffer bb
        {
            int nk = kt + 2;
            if (nk < 32) {
                load_kv(nk, bb);
            }
            cp_commit();
        }

        // (f) O += P * V
#pragma unroll
        for (int k2 = 0; k2 < 8; k2++) {
            uint32_t af[4];
            {
                int u  = 2 * k2 + gA;
                int uu = (u & 8) | ((u & 7) ^ (arow & 7));
                ldsm4(af[0], af[1], af[2], af[3],
                      su + (uint32_t)(AT_PS + arow * VT_STRIDE + uu * 16));
            }
            uint32_t vf[8][4];
#pragma unroll
            for (int jp = 0; jp < 8; jp++) {
                int r  = jp * 16 + brow;
                int u  = 2 * k2 + gB;
                int uu = (u & 8) | ((u & 7) ^ (r & 7));
                ldsm4(vf[jp][0], vf[jp][1], vf[jp][2], vf[jp][3],
                      su + (uint32_t)(AT_VT + r * VT_STRIDE + uu * 16));
            }
#pragma unroll
            for (int nt = 0; nt < 16; nt++) {
                mma_tf32(oacc[nt], af,
                         vf[nt >> 1][(nt & 1) * 2], vf[nt >> 1][(nt & 1) * 2 + 1]);
            }
        }
    }

    // epilogue
    {
        float r0 = 1.f / l0;
        float r1 = 1.f / l1;
        const int g  = lane >> 2;
        const int t2 = (lane & 3) * 2;
        int row0 = q0 + warp * 16 + g;
        float* op0 = O + (long)(b * SEQ + row0) * DIM + h * HD;
        float* op1 = op0 + (long)8 * DIM;
#pragma unroll
        for (int nt = 0; nt < 16; nt++) {
            *(float2*)(op0 + nt * 8 + t2) = make_float2(oacc[nt][0] * r0, oacc[nt][1] * r0);
            *(float2*)(op1 + nt * 8 + t2) = make_float2(oacc[nt][2] * r1, oacc[nt][3] * r1);
        }
    }
}

// ==================================================================
// Launch
// ==================================================================
extern "C" void kernel_launch(void* const* d_in, const int* in_sizes, int n_in,
                              void* d_out, int out_size)
{
    (void)in_sizes;
    (void)n_in;
    (void)out_size;
    const float* x  = (const float*)d_in[0];
    const float* wq = (const float*)d_in[1];
    const float* wk = (const float*)d_in[2];
    const float* wv = (const float*)d_in[3];
    const float* wo = (const float*)d_in[4];
    const int*   sp = (const int*)d_in[5];
    float* out = (float*)d_out;

    float* q;
    float* k;
    float* v;
    float* attn;
    float* rx;
    float* rwq;
    float* rwk;
    float* rwv;
    float* rwo;
    cudaGetSymbolAddress((void**)&q,    g_q);
    cudaGetSymbolAddress((void**)&k,    g_k);
    cudaGetSymbolAddress((void**)&v,    g_v);
    cudaGetSymbolAddress((void**)&attn, g_attn);
    cudaGetSymbolAddress((void**)&rx,   g_rx);
    cudaGetSymbolAddress((void**)&rwq,  g_rwq);
    cudaGetSymbolAddress((void**)&rwk,  g_rwk);
    cudaGetSymbolAddress((void**)&rwv,  g_rwv);
    cudaGetSymbolAddress((void**)&rwo,  g_rwo);

    cudaFuncSetAttribute(gemm_tf32,
                         cudaFuncAttributeMaxDynamicSharedMemorySize, GEMM_SMEM);
    cudaFuncSetAttribute(attn_tc_kernel,
                         cudaFuncAttributeMaxDynamicSharedMemorySize, ATTN_SMEM);

    {
        int n4x  = MROWS * DIM / 4;
        int n4q  = DIM * DIM / 4;
        int n4kv = KV_DIM * DIM / 4;
        round_tf32_kernel<<<(n4x  + 255) / 256, 256>>>(x,  rx,  n4x);
        round_tf32_kernel<<<(n4q  + 255) / 256, 256>>>(wq, rwq, n4q);
        round_tf32_kernel<<<(n4kv + 255) / 256, 256>>>(wk, rwk, n4kv);
        round_tf32_kernel<<<(n4kv + 255) / 256, 256>>>(wv, rwv, n4kv);
        round_tf32_kernel<<<(n4q  + 255) / 256, 256>>>(wo, rwo, n4q);
    }

    dim3 gq(DIM / GBN, MROWS / GBM);
    dim3 gkv(KV_DIM / GBN, MROWS / GBM);
    gemm_tf32<<<gq,  256, GEMM_SMEM>>>(rx, rwq, q, MROWS, DIM,    DIM);
    gemm_tf32<<<gkv, 256, GEMM_SMEM>>>(rx, rwk, k, MROWS, KV_DIM, DIM);
    gemm_tf32<<<gkv, 256, GEMM_SMEM>>>(rx, rwv, v, MROWS, KV_DIM, DIM);

    // rope rounds to tf32; q additionally pre-scaled by 1/sqrt(HD)
    rope_kernel<<<(MROWS * NHQ * 64) / 256, 256>>>(q, sp, NHQ, DIM, 0.08838834764831845f);
    rope_kernel<<<(MROWS * NHK * 64) / 256, 256>>>(k, sp, NHK, KV_DIM, 1.0f);
    // v to tf32 (in place)
    {
        int n4v = MROWS * KV_DIM / 4;
        round_tf32_kernel<<<(n4v + 255) / 256, 256>>>(v, v, n4v);
    }

    dim3 ga(SEQ / 128, NHQ, BATCH);
    attn_tc_kernel<<<ga, 256, ATTN_SMEM>>>(q, k, v, attn);

    {
        int n4x = MROWS * DIM / 4;
        round_tf32_kernel<<<(n4x + 255) / 256, 256>>>(attn, rx, n4x);
    }
    gemm_tf32<<<gq, 256, GEMM_SMEM>>>(rx, rwo, out, MROWS, DIM, DIM);
}

// round 8
// speedup vs baseline: 2.8957x; 1.1033x over previous
#include <cuda_runtime.h>
#include <cuda_fp16.h>
#include <cstdint>
#include <math.h>

#define BATCH 2
#define SEQ   2048
#define DIM   4096
#define KV_DIM 1024
#define NHQ   32
#define NHK   8
#define HD    128
#define MROWS (BATCH*SEQ)

// scratch (no allocations allowed)
__device__ float g_q[MROWS*DIM];
__device__ float g_k[MROWS*KV_DIM];
__device__ float g_v[MROWS*KV_DIM];
__device__ float g_attn[MROWS*DIM];
__device__ __half g_hx[MROWS*DIM];
__device__ __half g_hwq[DIM*DIM];
__device__ __half g_hwk[KV_DIM*DIM];
__device__ __half g_hwv[KV_DIM*DIM];
__device__ __half g_hwo[DIM*DIM];

// ==================================================================
// helpers
// ==================================================================
__device__ __forceinline__ uint32_t f2tf32(float x)
{
    uint32_t u;
    asm("cvt.rna.tf32.f32 %0, %1;" : "=r"(u) : "f"(x));
    return u;
}

__device__ __forceinline__ void ldsm4(uint32_t& r0, uint32_t& r1,
                                      uint32_t& r2, uint32_t& r3, uint32_t addr)
{
    asm volatile("ldmatrix.sync.aligned.m8n8.x4.shared.b16 {%0,%1,%2,%3}, [%4];"
                 : "=r"(r0), "=r"(r1), "=r"(r2), "=r"(r3) : "r"(addr));
}

__device__ __forceinline__ void mma_tf32(float* d, const uint32_t* a,
                                         uint32_t b0, uint32_t b1)
{
    asm volatile("mma.sync.aligned.m16n8k8.row.col.f32.tf32.tf32.f32 "
                 "{%0,%1,%2,%3},{%4,%5,%6,%7},{%8,%9},{%0,%1,%2,%3};"
                 : "+f"(d[0]), "+f"(d[1]), "+f"(d[2]), "+f"(d[3])
                 : "r"(a[0]), "r"(a[1]), "r"(a[2]), "r"(a[3]),
                   "r"(b0), "r"(b1));
}

__device__ __forceinline__ void mma_f16(float* d, const uint32_t* a,
                                        uint32_t b0, uint32_t b1)
{
    asm volatile("mma.sync.aligned.m16n8k16.row.col.f32.f16.f16.f32 "
                 "{%0,%1,%2,%3},{%4,%5,%6,%7},{%8,%9},{%0,%1,%2,%3};"
                 : "+f"(d[0]), "+f"(d[1]), "+f"(d[2]), "+f"(d[3])
                 : "r"(a[0]), "r"(a[1]), "r"(a[2]), "r"(a[3]),
                   "r"(b0), "r"(b1));
}

__device__ __forceinline__ void cp_async16(uint32_t dst, const void* src)
{
    asm volatile("cp.async.cg.shared.global [%0], [%1], 16;" :: "r"(dst), "l"(src));
}
__device__ __forceinline__ void cp_commit()
{
    asm volatile("cp.async.commit_group;");
}
template<int N> __device__ __forceinline__ void cp_wait()
{
    asm volatile("cp.async.wait_group %0;" :: "n"(N));
}

// ==================================================================
// conversion kernels
// ==================================================================
__global__ void round_tf32_kernel(const float* __restrict__ in,
                                  float* __restrict__ out, int n4)
{
    int i = blockIdx.x * blockDim.x + threadIdx.x;
    if (i < n4) {
        float4 v = ((const float4*)in)[i];
        uint4 u = make_uint4(f2tf32(v.x), f2tf32(v.y), f2tf32(v.z), f2tf32(v.w));
        ((uint4*)out)[i] = u;
    }
}

__global__ void to_half_kernel(const float* __restrict__ in,
                               __half* __restrict__ out, int n4)
{
    int i = blockIdx.x * blockDim.x + threadIdx.x;
    if (i < n4) {
        float4 v = ((const float4*)in)[i];
        __half2 h0 = __floats2half2_rn(v.x, v.y);
        __half2 h1 = __floats2half2_rn(v.z, v.w);
        ((__half2*)out)[i * 2]     = h0;
        ((__half2*)out)[i * 2 + 1] = h1;
    }
}

// ==================================================================
// FP16 GEMM (NT): C[M,N] = A[M,K] * B[N,K]^T, fp32 accumulate.
// 128x128x64(halves) tile, 256 threads = 8 warps (4M x 2N), warp 32x64.
// 3-stage cp.async, 128B swizzled rows, ldmatrix x4 frags, m16n8k16.
// ==================================================================
#define HBM 128
#define HBN 128
#define HBK 64
#define HSTAGES 3
#define HSTAGE_BYTES 32768
#define HGEMM_SMEM (HSTAGES*HSTAGE_BYTES)

__global__ __launch_bounds__(256, 2)
void gemm_f16(const __half* __restrict__ A, const __half* __restrict__ B,
              float* __restrict__ C, int M, int N, int K)
{
    extern __shared__ char hsm[];
    const uint32_t su = (uint32_t)__cvta_generic_to_shared(hsm);

    const int tid  = threadIdx.x;
    const int lane = tid & 31;
    const int warp = tid >> 5;
    const int wm   = warp & 3;
    const int wn   = warp >> 2;
    const int bm   = blockIdx.y;
    const int bn   = blockIdx.x;

    // loader: each thread 4 units (16B each) of one A row and one B row
    const int lrow = tid >> 1;           // 0..127
    const int lu0  = (tid & 1) * 4;      // 0 or 4
    const __half* Ap = A + (long)(bm * HBM + lrow) * K;
    const __half* Bp = B + (long)(bn * HBN + lrow) * K;
    const uint32_t aDst = su + (uint32_t)(lrow * 128);
    const uint32_t bDst = aDst + 16384u;
    const int lsw = lrow & 7;

    // fragment lane constants (same mapping for A and B in fp16 m16n8k16)
    const int grp = lane >> 3;
    const int lr  = lane & 7;
    const int frow = lr + 8 * (grp & 1);
    const int gk   = grp >> 1;           // k-half selector
    const int rowA = wm * 32 + frow;
    const int rowB = wn * 64 + frow;
    const int swA = rowA & 7;
    const int swB = rowB & 7;
    const uint32_t aRowOff = (uint32_t)rowA * 128u;
    const uint32_t bRowOff = (uint32_t)rowB * 128u;

    float c[2][8][4];
    for (int mt = 0; mt < 2; mt++) {
        for (int nt = 0; nt < 8; nt++) {
            for (int r = 0; r < 4; r++) {
                c[mt][nt][r] = 0.f;
            }
        }
    }

    const int T = K / HBK;

    // prologue
    for (int s = 0; s < HSTAGES - 1; s++) {
        int k0 = s * HBK;
        uint32_t ad = aDst + (uint32_t)s * HSTAGE_BYTES;
        uint32_t bd = bDst + (uint32_t)s * HSTAGE_BYTES;
#pragma unroll
        for (int p = 0; p < 4; p++) {
            int u = lu0 + p;
            uint32_t so = (uint32_t)((u ^ lsw) << 4);
            cp_async16(ad + so, Ap + k0 + u * 8);
            cp_async16(bd + so, Bp + k0 + u * 8);
        }
        cp_commit();
    }

    for (int ks = 0; ks < T; ks++) {
        cp_wait<HSTAGES - 2>();
        __syncthreads();

        int nk = ks + HSTAGES - 1;
        if (nk < T) {
            int slot = nk % HSTAGES;
            int k0 = nk * HBK;
            uint32_t ad = aDst + (uint32_t)slot * HSTAGE_BYTES;
            uint32_t bd = bDst + (uint32_t)slot * HSTAGE_BYTES;
#pragma unroll
            for (int p = 0; p < 4; p++) {
                int u = lu0 + p;
                uint32_t so = (uint32_t)((u ^ lsw) << 4);
                cp_async16(ad + so, Ap + k0 + u * 8);
                cp_async16(bd + so, Bp + k0 + u * 8);
            }
            cp_commit();
        }

        const uint32_t Abase = su + (uint32_t)((ks % HSTAGES) * HSTAGE_BYTES);
        const uint32_t Bbase = Abase + 16384u;

#pragma unroll
        for (int kk = 0; kk < 4; kk++) {
            int u = kk * 2 + gk;
            uint32_t af0[4];
            uint32_t af1[4];
            uint32_t aAddr = Abase + aRowOff + (uint32_t)(((u ^ swA) & 7) << 4) +
                             (uint32_t)((u & 8) << 4);
            ldsm4(af0[0], af0[1], af0[2], af0[3], aAddr);
            ldsm4(af1[0], af1[1], af1[2], af1[3], aAddr + 2048u);

            uint32_t bf[4][4];
#pragma unroll
            for (int jp = 0; jp < 4; jp++) {
                uint32_t bAddr = Bbase + bRowOff + (uint32_t)(jp * 2048) +
                                 (uint32_t)(((u ^ swB) & 7) << 4) +
                                 (uint32_t)((u & 8) << 4);
                ldsm4(bf[jp][0], bf[jp][1], bf[jp][2], bf[jp][3], bAddr);
            }

#pragma unroll
            for (int nt = 0; nt < 8; nt++) {
                uint32_t b0 = bf[nt >> 1][nt & 1];
                uint32_t b1 = bf[nt >> 1][(nt & 1) + 2];
                mma_f16(c[0][nt], af0, b0, b1);
                mma_f16(c[1][nt], af1, b0, b1);
            }
        }
    }

    const int g  = lane >> 2;
    const int t2 = (lane & 3) * 2;
    for (int mt = 0; mt < 2; mt++) {
        int row0 = bm * HBM + wm * 32 + mt * 16 + g;
        for (int nt = 0; nt < 8; nt++) {
            int col = bn * HBN + wn * 64 + nt * 8 + t2;
            *(float2*)(C + (long)row0 * N + col)       = make_float2(c[mt][nt][0], c[mt][nt][1]);
            *(float2*)(C + (long)(row0 + 8) * N + col) = make_float2(c[mt][nt][2], c[mt][nt][3]);
        }
    }
}

// ==================================================================
// RoPE: pre-scales (q) and rounds output to tf32 — unchanged R6
// ==================================================================
__global__ void rope_kernel(float* __restrict__ x, const int* __restrict__ sp,
                            int nh, int stride, float scale)
{
    int idx = blockIdx.x * blockDim.x + threadIdx.x;
    int i   = idx & 63;
    int h   = (idx >> 6) % nh;
    int row = idx / (64 * nh);
    int pos = (row % SEQ) + sp[0];

    float invf = (float)pow(10000.0, -(double)i / 64.0);
    float ang  = __fmul_rn((float)pos, invf);
    float sn;
    float cs;
    sincosf(ang, &sn, &cs);

    float2* p = (float2*)(x + (long)row * stride + h * HD);
    float2 v = p[i];
    float o0 = (v.x * cs - v.y * sn) * scale;
    float o1 = (v.x * sn + v.y * cs) * scale;
    p[i] = make_float2(__uint_as_float(f2tf32(o0)), __uint_as_float(f2tf32(o1)));
}

// ==================================================================
// Tensor-core flash attention (tf32 MMA, fp32 softmax) — unchanged R6
// ==================================================================
#define AT_VRAW  65536
#define AT_VT    131072
#define AT_PS    167936
#define VT_STRIDE 288
#define ATTN_SMEM (167936 + 128*288)

__global__ __launch_bounds__(256, 1)
void attn_tc_kernel(const float* __restrict__ Q, const float* __restrict__ Kg,
                    const float* __restrict__ Vg, float* __restrict__ O)
{
    extern __shared__ char smc[];
    const uint32_t su = (uint32_t)__cvta_generic_to_shared(smc);
    const int tid  = threadIdx.x;
    const int lane = tid & 31;
    const int warp = tid >> 5;
    const int qt = blockIdx.x;
    const int h  = blockIdx.y;
    const int b  = blockIdx.z;
    const int hk = h >> 2;
    const int q0 = qt * 128;

    const int grp = lane >> 3;
    const int lr  = lane & 7;
    const int arow = warp * 16 + lr + 8 * (grp & 1);
    const int gA   = grp >> 1;
    const int brow = lr + 8 * (grp >> 1);
    const int gB   = grp & 1;

    {
        int row = tid >> 1;
        int ub  = (tid & 1) * 16;
        const float* src = Q + (long)(b * SEQ + q0 + row) * DIM + h * HD;
#pragma unroll
        for (int p = 0; p < 16; p++) {
            int u  = ub + p;
            int uu = (u & 24) | ((u & 7) ^ (row & 7));
            cp_async16(su + (uint32_t)(row * 512 + uu * 16), src + u * 4);
        }
        cp_commit();
        cp_wait<0>();
        __syncthreads();
    }
    uint32_t qf[16][4];
    {
        uint32_t base = su + (uint32_t)(arow * 512);
#pragma unroll
        for (int kk = 0; kk < 16; kk++) {
            int u  = 2 * kk + gA;
            int uu = (u & 24) | ((u & 7) ^ (arow & 7));
            ldsm4(qf[kk][0], qf[kk][1], qf[kk][2], qf[kk][3], base + (uint32_t)(uu * 16));
        }
    }
    __syncthreads();

    float oacc[16][4];
    for (int nt = 0; nt < 16; nt++) {
        for (int r = 0; r < 4; r++) {
            oacc[nt][r] = 0.f;
        }
    }
    float m0 = -1e30f, m1 = -1e30f, l0 = 0.f, l1 = 0.f;

    const int lkrow = tid >> 2;
    const int lku   = tid & 3;

    auto load_kv = [&](int kt2, int bb2) {
        long roff = (long)(b * SEQ + kt2 * 64 + lkrow);
        const float* ks = Kg + roff * KV_DIM + hk * HD;
        const float* vs = Vg + roff * KV_DIM + hk * HD;
        uint32_t kd = su + (uint32_t)(bb2 * 32768 + lkrow * 512);
        uint32_t vd = su + (uint32_t)(AT_VRAW + bb2 * 32768 + lkrow * 512);
#pragma unroll
        for (int p = 0; p < 8; p++) {
            int u  = lku + p * 4;
            int uu = (u & 24) | ((u & 7) ^ (lkrow & 7));
            cp_async16(kd + (uint32_t)(uu * 16), ks + u * 4);
            cp_async16(vd + (uint32_t)(uu * 16), vs + u * 4);
        }
    };

    load_kv(0, 0);
    cp_commit();
    load_kv(1, 1);
    cp_commit();

    for (int kt = 0; kt < 32; kt++) {
        cp_wait<1>();
        __syncthreads();

        int bb = kt & 1;
        const uint32_t Kbase = su + (uint32_t)(bb * 32768);
        const int vrawOff = AT_VRAW + bb * 32768;

#pragma unroll
        for (int i = 0; i < 8; i++) {
            int idx = tid + i * 256;
            int r = idx >> 5;
            int u = idx & 31;
            int uu = (u & 24) | ((u & 7) ^ (r & 7));
            float4 v = *(const float4*)(smc + vrawOff + r * 512 + uu * 16);
            int d0  = u * 4;
            int vu  = r >> 2;
            int sub = r & 3;
            float vv4[4] = {v.x, v.y, v.z, v.w};
#pragma unroll
            for (int j = 0; j < 4; j++) {
                int d  = d0 + j;
                int vv = (vu & 8) | ((vu & 7) ^ (d & 7));
                *(float*)(smc + AT_VT + d * VT_STRIDE + vv * 16 + sub * 4) = vv4[j];
            }
        }

        float sc[8][4];
        for (int nt = 0; nt < 8; nt++) {
            for (int r = 0; r < 4; r++) {
                sc[nt][r] = 0.f;
            }
        }
#pragma unroll
        for (int kk = 0; kk < 16; kk++) {
            uint32_t bf[4][4];
#pragma unroll
            for (int jp = 0; jp < 4; jp++) {
                int r  = jp * 16 + brow;
                int u  = 2 * kk + gB;
                int uu = (u & 24) | ((u & 7) ^ (r & 7));
                ldsm4(bf[jp][0], bf[jp][1], bf[jp][2], bf[jp][3],
                      Kbase + (uint32_t)(r * 512 + uu * 16));
            }
#pragma unroll
            for (int nt = 0; nt < 8; nt++) {
                mma_tf32(sc[nt], qf[kk],
                         bf[nt >> 1][(nt & 1) * 2], bf[nt >> 1][(nt & 1) * 2 + 1]);
            }
        }

        {
            float mx0 = -1e30f, mx1 = -1e30f;
#pragma unroll
            for (int nt = 0; nt < 8; nt++) {
                mx0 = fmaxf(mx0, fmaxf(sc[nt][0], sc[nt][1]));
                mx1 = fmaxf(mx1, fmaxf(sc[nt][2], sc[nt][3]));
            }
            mx0 = fmaxf(mx0, __shfl_xor_sync(0xffffffffu, mx0, 1));
            mx0 = fmaxf(mx0, __shfl_xor_sync(0xffffffffu, mx0, 2));
            mx1 = fmaxf(mx1, __shfl_xor_sync(0xffffffffu, mx1, 1));
            mx1 = fmaxf(mx1, __shfl_xor_sync(0xffffffffu, mx1, 2));
            float nm0 = fmaxf(m0, mx0);
            float nm1 = fmaxf(m1, mx1);
            float cf0 = __expf(m0 - nm0);
            float cf1 = __expf(m1 - nm1);
            m0 = nm0;
            m1 = nm1;

            const int g  = lane >> 2;
            const int t2 = (lane & 3) * 2;
            const int prow0 = warp * 16 + g;
            const int prow1 = prow0 + 8;
            float ps0 = 0.f, ps1 = 0.f;
#pragma unroll
            for (int nt = 0; nt < 8; nt++) {
                float p0 = __expf(sc[nt][0] - nm0);
                float p1 = __expf(sc[nt][1] - nm0);
                float p2 = __expf(sc[nt][2] - nm1);
                float p3 = __expf(sc[nt][3] - nm1);
                ps0 += p0 + p1;
                ps1 += p2 + p3;
                int pu  = nt * 2 + (t2 >> 2);
                int pu0 = (pu & 8) | ((pu & 7) ^ (prow0 & 7));
                int pu1 = (pu & 8) | ((pu & 7) ^ (prow1 & 7));
                *(uint2*)(smc + AT_PS + prow0 * VT_STRIDE + pu0 * 16 + (t2 & 3) * 4) =
                    make_uint2(f2tf32(p0), f2tf32(p1));
                *(uint2*)(smc + AT_PS + prow1 * VT_STRIDE + pu1 * 16 + (t2 & 3) * 4) =
                    make_uint2(f2tf32(p2), f2tf32(p3));
            }
            ps0 += __shfl_xor_sync(0xffffffffu, ps0, 1);
            ps0 += __shfl_xor_sync(0xffffffffu, ps0, 2);
            ps1 += __shfl_xor_sync(0xffffffffu, ps1, 1);
            ps1 += __shfl_xor_sync(0xffffffffu, ps1, 2);
            l0 = l0 * cf0 + ps0;
            l1 = l1 * cf1 + ps1;
#pragma unroll
            for (int nt = 0; nt < 16; nt++) {
                oacc[nt][0] *= cf0;
                oacc[nt][1] *= cf0;
                oacc[nt][2] *= cf1;
                oacc[nt][3] *= cf1;
            }
        }
        __syncthreads();

        {
            int nk = kt + 2;
            if (nk < 32) {
                load_kv(nk, bb);
            }
            cp_commit();
        }

#pragma unroll
        for (int k2 = 0; k2 < 8; k2++) {
            uint32_t af[4];
            {
                int u  = 2 * k2 + gA;
                int uu = (u & 8) | ((u & 7) ^ (arow & 7));
                ldsm4(af[0], af[1], af[2], af[3],
                      su + (uint32_t)(AT_PS + arow * VT_STRIDE + uu * 16));
            }
            uint32_t vf[8][4];
#pragma unroll
            for (int jp = 0; jp < 8; jp++) {
                int r  = jp * 16 + brow;
                int u  = 2 * k2 + gB;
                int uu = (u & 8) | ((u & 7) ^ (r & 7));
                ldsm4(vf[jp][0], vf[jp][1], vf[jp][2], vf[jp][3],
                      su + (uint32_t)(AT_VT + r * VT_STRIDE + uu * 16));
            }
#pragma unroll
            for (int nt = 0; nt < 16; nt++) {
                mma_tf32(oacc[nt], af,
                         vf[nt >> 1][(nt & 1) * 2], vf[nt >> 1][(nt & 1) * 2 + 1]);
            }
        }
    }

    {
        float r0 = 1.f / l0;
        float r1 = 1.f / l1;
        const int g  = lane >> 2;
        const int t2 = (lane & 3) * 2;
        int row0 = q0 + warp * 16 + g;
        float* op0 = O + (long)(b * SEQ + row0) * DIM + h * HD;
        float* op1 = op0 + (long)8 * DIM;
#pragma unroll
        for (int nt = 0; nt < 16; nt++) {
            *(float2*)(op0 + nt * 8 + t2) = make_float2(oacc[nt][0] * r0, oacc[nt][1] * r0);
            *(float2*)(op1 + nt * 8 + t2) = make_float2(oacc[nt][2] * r1, oacc[nt][3] * r1);
        }
    }
}

// ==================================================================
// Launch
// ==================================================================
extern "C" void kernel_launch(void* const* d_in, const int* in_sizes, int n_in,
                              void* d_out, int out_size)
{
    (void)in_sizes;
    (void)n_in;
    (void)out_size;
    const float* x  = (const float*)d_in[0];
    const float* wq = (const float*)d_in[1];
    const float* wk = (const float*)d_in[2];
    const float* wv = (const float*)d_in[3];
    const float* wo = (const float*)d_in[4];
    const int*   sp = (const int*)d_in[5];
    float* out = (float*)d_out;

    float* q;
    float* k;
    float* v;
    float* attn;
    __half* hx;
    __half* hwq;
    __half* hwk;
    __half* hwv;
    __half* hwo;
    cudaGetSymbolAddress((void**)&q,    g_q);
    cudaGetSymbolAddress((void**)&k,    g_k);
    cudaGetSymbolAddress((void**)&v,    g_v);
    cudaGetSymbolAddress((void**)&attn, g_attn);
    cudaGetSymbolAddress((void**)&hx,   g_hx);
    cudaGetSymbolAddress((void**)&hwq,  g_hwq);
    cudaGetSymbolAddress((void**)&hwk,  g_hwk);
    cudaGetSymbolAddress((void**)&hwv,  g_hwv);
    cudaGetSymbolAddress((void**)&hwo,  g_hwo);

    cudaFuncSetAttribute(gemm_f16,
                         cudaFuncAttributeMaxDynamicSharedMemorySize, HGEMM_SMEM);
    cudaFuncSetAttribute(attn_tc_kernel,
                         cudaFuncAttributeMaxDynamicSharedMemorySize, ATTN_SMEM);

    {
        int n4x  = MROWS * DIM / 4;
        int n4q  = DIM * DIM / 4;
        int n4kv = KV_DIM * DIM / 4;
        to_half_kernel<<<(n4x  + 255) / 256, 256>>>(x,  hx,  n4x);
        to_half_kernel<<<(n4q  + 255) / 256, 256>>>(wq, hwq, n4q);
        to_half_kernel<<<(n4kv + 255) / 256, 256>>>(wk, hwk, n4kv);
        to_half_kernel<<<(n4kv + 255) / 256, 256>>>(wv, hwv, n4kv);
        to_half_kernel<<<(n4q  + 255) / 256, 256>>>(wo, hwo, n4q);
    }

    dim3 gq(DIM / HBN, MROWS / HBM);      // (32, 32)
    dim3 gkv(KV_DIM / HBN, MROWS / HBM);  // (8, 32)
    gemm_f16<<<gq,  256, HGEMM_SMEM>>>(hx, hwq, q, MROWS, DIM,    DIM);
    gemm_f16<<<gkv, 256, HGEMM_SMEM>>>(hx, hwk, k, MROWS, KV_DIM, DIM);
    gemm_f16<<<gkv, 256, HGEMM_SMEM>>>(hx, hwv, v, MROWS, KV_DIM, DIM);

    rope_kernel<<<(MROWS * NHQ * 64) / 256, 256>>>(q, sp, NHQ, DIM, 0.08838834764831845f);
    rope_kernel<<<(MROWS * NHK * 64) / 256, 256>>>(k, sp, NHK, KV_DIM, 1.0f);
    {
        int n4v = MROWS * KV_DIM / 4;
        round_tf32_kernel<<<(n4v + 255) / 256, 256>>>(v, v, n4v);
    }

    dim3 ga(SEQ / 128, NHQ, BATCH);
    attn_tc_kernel<<<ga, 256, ATTN_SMEM>>>(q, k, v, attn);

    {
        int n4x = MROWS * DIM / 4;
        to_half_kernel<<<(n4x + 255) / 256, 256>>>(attn, hx, n4x);
    }
    gemm_f16<<<gq, 256, HGEMM_SMEM>>>(hx, hwo, out, MROWS, DIM, DIM);
}